// round 2
// baseline (speedup 1.0000x reference)
#include <cuda_runtime.h>
#include <math.h>

// Problem constants
#define S    64
#define NSQ  32
#define NSQC 16
#define LL   2048
#define CC   512
#define EE   128
#define HOUT_ELEMS (S*NSQ*LL)      // 4194304

typedef unsigned long long u64;

// ---------------- scratch (device globals; no allocations allowed) ----------
__device__ float g_w[S*CC*3];                    // dyn conv weights [s][c][k]
__device__ float g_b[S*CC];                      // dyn conv bias    [s][c]
__device__ float g_x[(size_t)S*CC*LL];           // 256 MB  x = relu(dwconv)
__device__ float g_y[(size_t)S*CC*LL];           // 256 MB  y = relu(W1 x + b1)

// ---------------- packed f32x2 helpers (Blackwell FFMA2) --------------------
__device__ __forceinline__ u64 pk2(float x, float y) {
    u64 r; asm("mov.b64 %0, {%1,%2};" : "=l"(r) : "f"(x), "f"(y)); return r;
}
__device__ __forceinline__ void fma2(u64 &d, u64 a, u64 b) {
    asm("fma.rn.f32x2 %0, %1, %2, %0;" : "+l"(d) : "l"(a), "l"(b));
}
__device__ __forceinline__ float2 unpk2(u64 v) {
    float x, y; asm("mov.b64 {%0, %1}, %2;" : "=f"(x), "=f"(y) : "l"(v));
    return make_float2(x, y);
}

// ============================================================================
// Kernel A: dynamic weights  w[s,c,k] = emb[s]·Wa[c*3+k] + ba ; b[s,c] likewise
// Also zero-inits logdet output (d_out is poisoned).
// grid = 64 blocks (one per sample), 256 threads
// ============================================================================
__global__ void dynw_kernel(const float* __restrict__ emb,
                            const float* __restrict__ Wa,
                            const float* __restrict__ ba,
                            const float* __restrict__ Wb,
                            const float* __restrict__ bb,
                            float* __restrict__ logdet)
{
    int s = blockIdx.x;
    __shared__ float e[EE];
    int t = threadIdx.x;
    if (t < EE) e[t] = emb[s*EE + t];
    __syncthreads();

    for (int r = t; r < CC*3 + CC; r += blockDim.x) {
        const float* row; float bias; float* outp;
        if (r < CC*3) { row = Wa + (size_t)r*EE;            bias = ba[r];  outp = &g_w[s*CC*3 + r]; }
        else          { int r2 = r - CC*3;
                        row = Wb + (size_t)r2*EE;           bias = bb[r2]; outp = &g_b[s*CC + r2]; }
        float acc = bias;
        #pragma unroll 8
        for (int k = 0; k < EE; ++k) acc = fmaf(e[k], row[k], acc);
        *outp = acc;
    }
    if (t == 0) logdet[s] = 0.f;
}

// ============================================================================
// Kernel B: x[s,c,l] = relu( sum_k h1[s, c>>5, l+k-1]*w[s,c,k] + b[s,c] )
// grid = (512, 64)  block=(c, s), 256 threads, 8 l's per thread
// ============================================================================
__global__ __launch_bounds__(256)
void dwconv_kernel(const float* __restrict__ h)
{
    int c = blockIdx.x, s = blockIdx.y;
    const float* __restrict__ hrow = h + ((size_t)s*NSQ + (c >> 5)) * LL;
    float w0 = g_w[s*CC*3 + c*3 + 0];
    float w1 = g_w[s*CC*3 + c*3 + 1];
    float w2 = g_w[s*CC*3 + c*3 + 2];
    float bb = g_b[s*CC + c];
    float* __restrict__ xrow = g_x + ((size_t)s*CC + c) * LL;

    int l0 = threadIdx.x * 8;
    float v[10];
    float4 f0 = *(const float4*)(hrow + l0);
    float4 f1 = *(const float4*)(hrow + l0 + 4);
    v[1]=f0.x; v[2]=f0.y; v[3]=f0.z; v[4]=f0.w;
    v[5]=f1.x; v[6]=f1.y; v[7]=f1.z; v[8]=f1.w;
    v[0] = (l0 > 0)        ? hrow[l0 - 1] : 0.f;
    v[9] = (l0 + 8 < LL)   ? hrow[l0 + 8] : 0.f;

    float r[8];
    #pragma unroll
    for (int j = 0; j < 8; ++j) {
        float a = fmaf(w0, v[j], fmaf(w1, v[j+1], fmaf(w2, v[j+2], bb)));
        r[j] = fmaxf(a, 0.f);
    }
    *(float4*)(xrow + l0)     = make_float4(r[0], r[1], r[2], r[3]);
    *(float4*)(xrow + l0 + 4) = make_float4(r[4], r[5], r[6], r[7]);
}

// ============================================================================
// Kernel C: per-sample GEMM  Y = relu(W1 * X + b1)
//   M=512 (o), N=2048 (l), K=512 (c); grid=(16 bn, 4 bm, 64 s)
//   128x128x8 tile, 256 threads, 8x8 microtile, FFMA2 (f32x2) accumulation,
//   double-buffered shared memory, one sync per k-tile.
// ============================================================================
__global__ __launch_bounds__(256, 2)
void gemm1_kernel(const float* __restrict__ W1, const float* __restrict__ b1)
{
    int bn = blockIdx.x, bm = blockIdx.y, s = blockIdx.z;
    const float* __restrict__ X = g_x + (size_t)s * (CC*LL);
    float* __restrict__ Y       = g_y + (size_t)s * (CC*LL);

    __shared__ float As[2][8][132];   // padded: conflict-free transposed stores
    __shared__ float Bs[2][8][128];

    int t  = threadIdx.x;
    int tx = t & 15, ty = t >> 4;

    int arow = t >> 1;            // 0..127
    int acol = (t & 1) * 4;       // 0 or 4
    int brow = t >> 5;            // 0..7
    int bcol = (t & 31) * 4;      // 0..124

    const float* Ap = W1 + (size_t)(bm*128 + arow)*CC + acol;
    const float* Bp = X + (size_t)brow*LL + bn*128 + bcol;

    float4 ra = *(const float4*)Ap;
    float4 rb = *(const float4*)Bp;

    u64 acc[8][4];
    #pragma unroll
    for (int i = 0; i < 8; ++i)
        #pragma unroll
        for (int j = 0; j < 4; ++j) acc[i][j] = 0ull;

    int buf = 0;
    As[0][acol+0][arow] = ra.x; As[0][acol+1][arow] = ra.y;
    As[0][acol+2][arow] = ra.z; As[0][acol+3][arow] = ra.w;
    *(float4*)&Bs[0][brow][bcol] = rb;
    __syncthreads();

    for (int kt = 0; kt < 64; ++kt) {
        if (kt < 63) {
            ra = *(const float4*)(Ap + (kt+1)*8);
            rb = *(const float4*)(Bp + (size_t)(kt+1)*8*LL);
        }
        #pragma unroll
        for (int kk = 0; kk < 8; ++kk) {
            ulonglong2 bq0 = *(const ulonglong2*)&Bs[buf][kk][tx*8];
            ulonglong2 bq1 = *(const ulonglong2*)&Bs[buf][kk][tx*8 + 4];
            float4 a0 = *(const float4*)&As[buf][kk][ty*8];
            float4 a1 = *(const float4*)&As[buf][kk][ty*8 + 4];
            u64 bp[4] = { bq0.x, bq0.y, bq1.x, bq1.y };
            u64 ap[8];
            ap[0]=pk2(a0.x,a0.x); ap[1]=pk2(a0.y,a0.y);
            ap[2]=pk2(a0.z,a0.z); ap[3]=pk2(a0.w,a0.w);
            ap[4]=pk2(a1.x,a1.x); ap[5]=pk2(a1.y,a1.y);
            ap[6]=pk2(a1.z,a1.z); ap[7]=pk2(a1.w,a1.w);
            #pragma unroll
            for (int i = 0; i < 8; ++i) {
                fma2(acc[i][0], ap[i], bp[0]);
                fma2(acc[i][1], ap[i], bp[1]);
                fma2(acc[i][2], ap[i], bp[2]);
                fma2(acc[i][3], ap[i], bp[3]);
            }
        }
        if (kt < 63) {
            As[buf^1][acol+0][arow] = ra.x; As[buf^1][acol+1][arow] = ra.y;
            As[buf^1][acol+2][arow] = ra.z; As[buf^1][acol+3][arow] = ra.w;
            *(float4*)&Bs[buf^1][brow][bcol] = rb;
            __syncthreads();
            buf ^= 1;
        }
    }

    #pragma unroll
    for (int i = 0; i < 8; ++i) {
        int o = bm*128 + ty*8 + i;
        float bias = b1[o];
        float r[8];
        #pragma unroll
        for (int j = 0; j < 4; ++j) {
            float2 p = unpk2(acc[i][j]);
            r[2*j]   = fmaxf(p.x + bias, 0.f);
            r[2*j+1] = fmaxf(p.y + bias, 0.f);
        }
        float* yp = Y + (size_t)o*LL + bn*128 + tx*8;
        *(float4*)yp       = make_float4(r[0], r[1], r[2], r[3]);
        *(float4*)(yp + 4) = make_float4(r[4], r[5], r[6], r[7]);
    }
}

// ============================================================================
// Kernel D: conv2 (3-tap, 512->32) + sigmoid gate + coupling + logdet + h1 copy
//   grid=(32 ltiles, 64 s), 256 threads, TL=64, y-tile (512 x 66) in smem.
//   thread: o2 = t&15 (s/m channel pair), lg = t>>4, 4 l's each.
// ============================================================================
__global__ __launch_bounds__(256)
void conv2_kernel(const float* __restrict__ h, const float* __restrict__ W2,
                  const float* __restrict__ b2, float* __restrict__ out)
{
    extern __shared__ float ysm[];     // [512][66]
    int lt = blockIdx.x, s = blockIdx.y;
    int l0 = lt * 64;
    const float* __restrict__ Ys = g_y + (size_t)s * (CC*LL);
    int t = threadIdx.x;

    for (int idx = t; idx < CC*66; idx += 256) {
        int c = idx / 66, li = idx - c*66;
        int gl = l0 - 1 + li;
        ysm[idx] = ((unsigned)gl < (unsigned)LL) ? Ys[(size_t)c*LL + gl] : 0.f;
    }
    __syncthreads();

    int o2 = t & 15, lg = t >> 4;
    float as0=0.f, as1=0.f, as2=0.f, as3=0.f;
    float am0=0.f, am1=0.f, am2=0.f, am3=0.f;
    const float* __restrict__ Ws = W2 + (size_t)o2 * (CC*3);
    const float* __restrict__ Wm = W2 + (size_t)(o2 + 16) * (CC*3);
    const float* __restrict__ yb = ysm + lg*4;   // li of (l0+lg*4-1)

    #pragma unroll 4
    for (int c = 0; c < CC; ++c) {
        const float* yp = yb + c*66;
        float y0=yp[0], y1=yp[1], y2=yp[2], y3=yp[3], y4=yp[4], y5=yp[5];
        float w0 = Ws[c*3], w1 = Ws[c*3+1], w2 = Ws[c*3+2];
        as0 = fmaf(w0,y0, fmaf(w1,y1, fmaf(w2,y2, as0)));
        as1 = fmaf(w0,y1, fmaf(w1,y2, fmaf(w2,y3, as1)));
        as2 = fmaf(w0,y2, fmaf(w1,y3, fmaf(w2,y4, as2)));
        as3 = fmaf(w0,y3, fmaf(w1,y4, fmaf(w2,y5, as3)));
        float m0 = Wm[c*3], m1 = Wm[c*3+1], m2 = Wm[c*3+2];
        am0 = fmaf(m0,y0, fmaf(m1,y1, fmaf(m2,y2, am0)));
        am1 = fmaf(m0,y1, fmaf(m1,y2, fmaf(m2,y3, am1)));
        am2 = fmaf(m0,y2, fmaf(m1,y3, fmaf(m2,y4, am2)));
        am3 = fmaf(m0,y3, fmaf(m1,y4, fmaf(m2,y5, am3)));
    }

    float bs = b2[o2], bm_ = b2[o2 + 16];
    float accs[4] = {as0, as1, as2, as3};
    float accm[4] = {am0, am1, am2, am3};
    float logsum = 0.f;
    size_t rowbase = ((size_t)s*NSQ + 16 + o2) * LL;
    #pragma unroll
    for (int j = 0; j < 4; ++j) {
        int l = l0 + lg*4 + j;
        float z  = accs[j] + bs + 2.0f;
        float sg = 1.f / (1.f + expf(-z)) + 1e-7f;
        float m  = accm[j] + bm_;
        float h2v = h[rowbase + l];
        out[rowbase + l] = sg * (h2v + m);
        logsum += logf(sg);
    }
    #pragma unroll
    for (int off = 16; off; off >>= 1)
        logsum += __shfl_xor_sync(0xffffffffu, logsum, off);
    if ((t & 31) == 0)
        atomicAdd(out + HOUT_ELEMS + s, logsum);

    // h1 passthrough copy for this l-tile
    for (int idx = t; idx < NSQC*64; idx += 256) {
        int ch = idx >> 6;
        int l  = l0 + (idx & 63);
        size_t off = ((size_t)s*NSQ + ch) * LL + l;
        out[off] = h[off];
    }
}

// ============================================================================
extern "C" void kernel_launch(void* const* d_in, const int* in_sizes, int n_in,
                              void* d_out, int out_size)
{
    const float* h   = (const float*)d_in[0];
    const float* emb = (const float*)d_in[1];
    const float* Wa  = (const float*)d_in[2];
    const float* ba  = (const float*)d_in[3];
    const float* Wb  = (const float*)d_in[4];
    const float* bb  = (const float*)d_in[5];
    const float* W1  = (const float*)d_in[6];
    const float* b1  = (const float*)d_in[7];
    const float* W2  = (const float*)d_in[8];
    const float* b2  = (const float*)d_in[9];
    float* out = (float*)d_out;

    static bool attr_set = false;
    if (!attr_set) {
        cudaFuncSetAttribute(conv2_kernel,
                             cudaFuncAttributeMaxDynamicSharedMemorySize,
                             CC*66*sizeof(float));
        attr_set = true;
    }

    dynw_kernel<<<S, 256>>>(emb, Wa, ba, Wb, bb, out + HOUT_ELEMS);
    dwconv_kernel<<<dim3(CC, S), 256>>>(h);
    gemm1_kernel<<<dim3(16, 4, S), 256>>>(W1, b1);
    conv2_kernel<<<dim3(32, S), 256, CC*66*sizeof(float)>>>(h, W2, b2, out);
}

// round 7
// speedup vs baseline: 4.1746x; 4.1746x over previous
#include <cuda_runtime.h>
#include <cuda_bf16.h>
#include <math.h>
#include <stdint.h>

// Problem constants
#define S    64
#define NSQ  32
#define NSQC 16
#define LL   2048
#define CC   512
#define EE   128
#define HOUT_ELEMS (S*NSQ*LL)      // 4194304

typedef unsigned long long u64;
typedef unsigned int u32;

// ---------------- scratch (device globals; no allocations allowed) ----------
__device__ float         g_w[S*CC*3];                 // dyn conv weights [s][c][k]
__device__ float         g_b[S*CC];                   // dyn conv bias    [s][c]
__device__ __nv_bfloat16 g_xh[(size_t)S*LL*CC];       // 128 MB  xT hi  [s][l][c]
__device__ __nv_bfloat16 g_xl[(size_t)S*LL*CC];       // 128 MB  xT lo
__device__ __nv_bfloat16 g_w1h[CC*CC];                // W1 hi bf16 [o][c]
__device__ __nv_bfloat16 g_w1l[CC*CC];                // W1 lo bf16
__device__ float         g_y[(size_t)S*CC*LL];        // 256 MB  y = relu(W1 x + b1)  [s][o][l]

// ---------------- packed f32x2 helpers --------------------------------------
__device__ __forceinline__ u64 pk2(float x, float y) {
    u64 r; asm("mov.b64 %0, {%1,%2};" : "=l"(r) : "f"(x), "f"(y)); return r;
}
__device__ __forceinline__ void fma2(u64 &d, u64 a, u64 b) {
    asm("fma.rn.f32x2 %0, %1, %2, %0;" : "+l"(d) : "l"(a), "l"(b));
}
__device__ __forceinline__ float2 unpk2(u64 v) {
    float x, y; asm("mov.b64 {%0, %1}, %2;" : "=f"(x), "=f"(y) : "l"(v));
    return make_float2(x, y);
}

// ---------------- mma / ldmatrix / cp.async helpers (sm_80-baseline ISA) ----
__device__ __forceinline__ u32 smem_u32(const void* p) {
    u32 a; asm("{ .reg .u64 t; cvta.to.shared.u64 t, %1; cvt.u32.u64 %0, t; }"
               : "=r"(a) : "l"(p));
    return a;
}
__device__ __forceinline__ void ldm4(u32* r, u32 addr) {
    asm volatile("ldmatrix.sync.aligned.m8n8.x4.shared.b16 {%0,%1,%2,%3}, [%4];"
                 : "=r"(r[0]), "=r"(r[1]), "=r"(r[2]), "=r"(r[3]) : "r"(addr));
}
__device__ __forceinline__ void mma16816(float* d, const u32* a, const u32* b) {
    asm volatile("mma.sync.aligned.m16n8k16.row.col.f32.bf16.bf16.f32 "
                 "{%0,%1,%2,%3}, {%4,%5,%6,%7}, {%8,%9}, {%0,%1,%2,%3};"
                 : "+f"(d[0]), "+f"(d[1]), "+f"(d[2]), "+f"(d[3])
                 : "r"(a[0]), "r"(a[1]), "r"(a[2]), "r"(a[3]), "r"(b[0]), "r"(b[1]));
}
#define CP16(sm, gp)  asm volatile("cp.async.cg.shared.global [%0], [%1], 16;" :: "r"(sm), "l"(gp))
#define CP_COMMIT()   asm volatile("cp.async.commit_group;" ::: "memory")
#define CP_WAIT0()    asm volatile("cp.async.wait_group 0;" ::: "memory")

// smem tile layout: 128 rows x 64 bytes (32 bf16), 16B chunks XOR-swizzled so
// any ldmatrix phase (8 rows, fixed chunk) and the cp.async stores are
// conflict-free:  slot(r,c) = (r&1)*4 + (c ^ ((r>>1)&3))
__device__ __forceinline__ u32 soff(int r, int c) {
    return (u32)(r*64 + ((c ^ ((r >> 1) & 3)) * 16));
}

// ============================================================================
// Kernel A: dynamic weights (emb GEMV) + zero logdet
// ============================================================================
__global__ void dynw_kernel(const float* __restrict__ emb,
                            const float* __restrict__ Wa,
                            const float* __restrict__ ba,
                            const float* __restrict__ Wb,
                            const float* __restrict__ bb,
                            float* __restrict__ logdet)
{
    int s = blockIdx.x;
    __shared__ float e[EE];
    int t = threadIdx.x;
    if (t < EE) e[t] = emb[s*EE + t];
    __syncthreads();

    for (int r = t; r < CC*3 + CC; r += blockDim.x) {
        const float* row; float bias; float* outp;
        if (r < CC*3) { row = Wa + (size_t)r*EE; bias = ba[r]; outp = &g_w[s*CC*3 + r]; }
        else { int r2 = r - CC*3; row = Wb + (size_t)r2*EE; bias = bb[r2]; outp = &g_b[s*CC + r2]; }
        float acc = bias;
        #pragma unroll 8
        for (int k = 0; k < EE; ++k) acc = fmaf(e[k], row[k], acc);
        *outp = acc;
    }
    if (t == 0) logdet[s] = 0.f;
}

// ============================================================================
// Kernel A2: W1 -> bf16 hi/lo split.  grid=512 (o), block=256
// ============================================================================
__global__ void w1cvt_kernel(const float* __restrict__ W1)
{
    int o = blockIdx.x, t = threadIdx.x;
    float2 v = *(const float2*)(W1 + (size_t)o*CC + t*2);
    unsigned short h0 = __bfloat16_as_ushort(__float2bfloat16_rn(v.x));
    unsigned short h1 = __bfloat16_as_ushort(__float2bfloat16_rn(v.y));
    float l0 = v.x - __bfloat162float(__float2bfloat16_rn(v.x));
    float l1 = v.y - __bfloat162float(__float2bfloat16_rn(v.y));
    unsigned short g0 = __bfloat16_as_ushort(__float2bfloat16_rn(l0));
    unsigned short g1 = __bfloat16_as_ushort(__float2bfloat16_rn(l1));
    ((u32*)g_w1h)[o*256 + t] = (u32)h0 | ((u32)h1 << 16);
    ((u32*)g_w1l)[o*256 + t] = (u32)g0 | ((u32)g1 << 16);
}

// ============================================================================
// Kernel B: depthwise conv -> relu -> bf16 hi/lo, TRANSPOSED layout xT[s][l][c]
// grid=(8 ltile, 8 ctile, 64 s), block=256 (one l per thread, 64 c's)
// ============================================================================
__global__ __launch_bounds__(256)
void dwconv_kernel(const float* __restrict__ h)
{
    int lt = blockIdx.x, ct = blockIdx.y, s = blockIdx.z;
    int t = threadIdx.x;
    int l = lt*256 + t;

    __shared__ float wsm[64][4];
    {
        int c = t >> 2, j = t & 3;
        int cg = ct*64 + c;
        wsm[c][j] = (j < 3) ? g_w[s*CC*3 + cg*3 + j] : g_b[s*CC + cg];
    }

    // two h1 rows feed this c-tile
    int r0 = ct * 2;
    const float* hp0 = h + ((size_t)s*NSQ + r0) * LL;
    const float* hp1 = h + ((size_t)s*NSQ + r0 + 1) * LL;
    float a0 = (l > 0)      ? hp0[l-1] : 0.f;
    float a1 = hp0[l];
    float a2 = (l < LL-1)   ? hp0[l+1] : 0.f;
    float b0 = (l > 0)      ? hp1[l-1] : 0.f;
    float b1v = hp1[l];
    float b2 = (l < LL-1)   ? hp1[l+1] : 0.f;
    __syncthreads();

    u32 hi[32], lo[32];
    #pragma unroll
    for (int p = 0; p < 32; ++p) {
        u32 hh = 0, ll2 = 0;
        #pragma unroll
        for (int q = 0; q < 2; ++q) {
            int i = p*2 + q;
            float w0 = wsm[i][0], w1 = wsm[i][1], w2 = wsm[i][2], bi = wsm[i][3];
            float v;
            if (i < 32) v = fmaf(w0, a0, fmaf(w1, a1, fmaf(w2, a2, bi)));
            else        v = fmaf(w0, b0, fmaf(w1, b1v, fmaf(w2, b2, bi)));
            v = fmaxf(v, 0.f);
            __nv_bfloat16 vh = __float2bfloat16_rn(v);
            float rem = v - __bfloat162float(vh);
            __nv_bfloat16 vl = __float2bfloat16_rn(rem);
            hh  |= ((u32)__bfloat16_as_ushort(vh)) << (q*16);
            ll2 |= ((u32)__bfloat16_as_ushort(vl)) << (q*16);
        }
        hi[p] = hh; lo[p] = ll2;
    }

    size_t base = ((size_t)s*LL + l) * CC + ct*64;    // element offset
    uint4* dh = (uint4*)(g_xh + base);
    uint4* dl = (uint4*)(g_xl + base);
    #pragma unroll
    for (int j = 0; j < 8; ++j) {
        dh[j] = make_uint4(hi[4*j], hi[4*j+1], hi[4*j+2], hi[4*j+3]);
        dl[j] = make_uint4(lo[4*j], lo[4*j+1], lo[4*j+2], lo[4*j+3]);
    }
}

// ============================================================================
// Kernel C: HMMA GEMM  Y = relu(W1 X + b1), bf16 3-term split, fp32 accum
//   per-sample GEMM M=512(o) N=2048(l) K=512(c)
//   CTA tile 128x128, K-chunk 32, double-buffered cp.async
//   8 warps = 4(m) x 2(n); warp tile 32x64; mma.sync.m16n8k16 bf16
//   grid=(16 bn, 4 bm, 64 s), 256 threads
// ============================================================================
#define GT_BYTES 8192                    // one 128x32 bf16 tile
// tile order within a buffer: Ah(0) Al(1) Bh(2) Bl(3); buffers at 0 / 32768
#define GSMEM_TOTAL 65536

__global__ __launch_bounds__(256)
void gemm_mma_kernel(const float* __restrict__ b1)
{
    extern __shared__ __align__(128) char smem[];
    u32 sb = smem_u32(smem);
    int t = threadIdx.x, lane = t & 31, wid = t >> 5;
    int bn = blockIdx.x, bm = blockIdx.y, s = blockIdx.z;
    int wm = wid & 3;          // 0..3 -> 32 m-rows each
    int wn = wid >> 2;         // 0..1 -> 64 n-cols each

    // per-thread load coords: 2 iterations x (row, chunk)
    int r_ld[2], c_ld[2];
    #pragma unroll
    for (int i = 0; i < 2; ++i) { int idx = t + i*256; r_ld[i] = idx >> 2; c_ld[i] = idx & 3; }

    const __nv_bfloat16* Ah = g_w1h;
    const __nv_bfloat16* Al = g_w1l;
    const __nv_bfloat16* Bh = g_xh + (size_t)s*LL*CC;
    const __nv_bfloat16* Bl = g_xl + (size_t)s*LL*CC;

    auto load_buf = [&](int buf, int kt) {
        u32 base = sb + buf*32768;
        int k0 = kt*32;
        #pragma unroll
        for (int i = 0; i < 2; ++i) {
            int r = r_ld[i], c = c_ld[i];
            u32 so = soff(r, c);
            size_t ka = (size_t)(bm*128 + r)*CC + k0 + c*8;
            size_t kb = (size_t)(bn*128 + r)*CC + k0 + c*8;
            CP16(base + 0*GT_BYTES + so, Ah + ka);
            CP16(base + 1*GT_BYTES + so, Al + ka);
            CP16(base + 2*GT_BYTES + so, Bh + kb);
            CP16(base + 3*GT_BYTES + so, Bl + kb);
        }
    };

    float acc[2][8][4];
    #pragma unroll
    for (int i = 0; i < 2; ++i)
        #pragma unroll
        for (int j = 0; j < 8; ++j)
            #pragma unroll
            for (int q = 0; q < 4; ++q) acc[i][j][q] = 0.f;

    load_buf(0, 0); CP_COMMIT();

    int buf = 0;
    for (int kt = 0; kt < 16; ++kt) {
        CP_WAIT0();
        __syncthreads();
        if (kt < 15) { load_buf(buf ^ 1, kt + 1); CP_COMMIT(); }

        u32 base = sb + buf*32768;
        #pragma unroll
        for (int ks = 0; ks < 2; ++ks) {
            // A fragments: 2 m16 tiles, hi & lo
            u32 a_h[2][4], a_l[2][4];
            #pragma unroll
            for (int ti = 0; ti < 2; ++ti) {
                int row = wm*32 + ti*16 + (lane & 15);
                int ch  = ks*2 + (lane >> 4);
                u32 so = soff(row, ch);
                ldm4(a_h[ti], base + 0*GT_BYTES + so);
                ldm4(a_l[ti], base + 1*GT_BYTES + so);
            }
            // B fragments: 8 n8 tiles (4 ldmatrix.x4 groups), hi & lo
            u32 b_h[8][2], b_l[8][2];
            #pragma unroll
            for (int g = 0; g < 4; ++g) {
                int row = wn*64 + g*16 + (lane & 7) + 8*(lane >> 4);
                int ch  = ks*2 + ((lane >> 3) & 1);
                u32 so = soff(row, ch);
                u32 rh[4], rl[4];
                ldm4(rh, base + 2*GT_BYTES + so);
                ldm4(rl, base + 3*GT_BYTES + so);
                b_h[2*g][0] = rh[0]; b_h[2*g][1] = rh[1];
                b_h[2*g+1][0] = rh[2]; b_h[2*g+1][1] = rh[3];
                b_l[2*g][0] = rl[0]; b_l[2*g][1] = rl[1];
                b_l[2*g+1][0] = rl[2]; b_l[2*g+1][1] = rl[3];
            }
            #pragma unroll
            for (int i = 0; i < 2; ++i)
                #pragma unroll
                for (int j = 0; j < 8; ++j) {
                    mma16816(acc[i][j], a_h[i], b_h[j]);
                    mma16816(acc[i][j], a_h[i], b_l[j]);
                    mma16816(acc[i][j], a_l[i], b_h[j]);
                }
        }
        buf ^= 1;
    }

    // ---- epilogue: relu(acc + bias) -> g_y [s][o][l] fp32 ----
    #pragma unroll
    for (int i = 0; i < 2; ++i) {
        int row = bm*128 + wm*32 + i*16 + (lane >> 2);
        float bias0 = b1[row], bias8 = b1[row + 8];
        float* y0 = g_y + ((size_t)s*CC + row)    *LL + bn*128 + wn*64;
        float* y8 = g_y + ((size_t)s*CC + row + 8)*LL + bn*128 + wn*64;
        int cofs = 2*(lane & 3);
        #pragma unroll
        for (int j = 0; j < 8; ++j) {
            float* d = acc[i][j];
            *(float2*)(y0 + j*8 + cofs) =
                make_float2(fmaxf(d[0] + bias0, 0.f), fmaxf(d[1] + bias0, 0.f));
            *(float2*)(y8 + j*8 + cofs) =
                make_float2(fmaxf(d[2] + bias8, 0.f), fmaxf(d[3] + bias8, 0.f));
        }
    }
}

// ============================================================================
// Kernel D: conv2 (3-tap, 512->32) + sigmoid + coupling + logdet + h1 copy
//   grid=(8 ltile(256 l), 64 s), 256 threads; c chunked by 64 through smem.
//   thread: o2 = t&15 (s,m channel pair), lg = t>>4, 16 l's each.
//   W2 pre-paired (w_s, w_m) float2 in smem -> one FFMA2 does both channels.
// ============================================================================
#define CONV2_YS   (64*258)                 // floats
#define CONV2_WOFF (CONV2_YS)               // float2 region starts here (8B aligned)
#define CONV2_SMEM ((CONV2_YS + 64*3*16*2) * 4)

__global__ __launch_bounds__(256, 2)
void conv2_kernel(const float* __restrict__ h, const float* __restrict__ W2,
                  const float* __restrict__ b2, float* __restrict__ out)
{
    extern __shared__ __align__(16) float csm[];
    float* ysm = csm;                        // [64][258]
    u64*   wsm = (u64*)(csm + CONV2_WOFF);   // [64][3][16] (w_s, w_m) pairs

    int lt = blockIdx.x, s = blockIdx.y;
    int l0 = lt * 256;
    const float* __restrict__ Ys = g_y + (size_t)s * (CC*LL);
    int t = threadIdx.x;
    int o2 = t & 15, lg = t >> 4;

    u64 acc[16];
    #pragma unroll
    for (int j = 0; j < 16; ++j) acc[j] = 0ull;

    for (int cc = 0; cc < 8; ++cc) {
        __syncthreads();
        for (int idx = t; idx < 64*258; idx += 256) {
            int r = idx / 258, i = idx - r*258;
            int gl = l0 + i - 1;
            ysm[idx] = ((unsigned)gl < (unsigned)LL)
                       ? Ys[(size_t)(cc*64 + r)*LL + gl] : 0.f;
        }
        for (int idx = t; idx < 64*3*16; idx += 256) {
            int oo = idx & 15, rk = idx >> 4;
            int k = rk % 3, r = rk / 3;
            int c = cc*64 + r;
            float a = W2[(size_t)oo      *(CC*3) + c*3 + k];
            float b = W2[(size_t)(oo+16) *(CC*3) + c*3 + k];
            wsm[(r*3 + k)*16 + oo] = pk2(a, b);
        }
        __syncthreads();

        const float* yb = ysm + lg*16;
        #pragma unroll 2
        for (int r = 0; r < 64; ++r) {
            const float* yp = yb + r*258;
            u64 yd[18];
            #pragma unroll
            for (int j = 0; j < 9; ++j) {
                float2 v = *(const float2*)(yp + 2*j);
                yd[2*j]   = pk2(v.x, v.x);
                yd[2*j+1] = pk2(v.y, v.y);
            }
            u64 w0 = wsm[(r*3 + 0)*16 + o2];
            u64 w1 = wsm[(r*3 + 1)*16 + o2];
            u64 w2 = wsm[(r*3 + 2)*16 + o2];
            #pragma unroll
            for (int j = 0; j < 16; ++j) {
                fma2(acc[j], w0, yd[j]);
                fma2(acc[j], w1, yd[j+1]);
                fma2(acc[j], w2, yd[j+2]);
            }
        }
    }

    float bs = b2[o2], bm_ = b2[o2 + 16];
    float logsum = 0.f;
    size_t rowbase = ((size_t)s*NSQ + 16 + o2) * LL;
    int lb = l0 + lg*16;
    #pragma unroll
    for (int j = 0; j < 16; ++j) {
        float2 p = unpk2(acc[j]);            // (s_acc, m_acc)
        float z  = p.x + bs + 2.0f;
        float sg = 1.f / (1.f + expf(-z)) + 1e-7f;
        float m  = p.y + bm_;
        float h2v = h[rowbase + lb + j];
        out[rowbase + lb + j] = sg * (h2v + m);
        logsum += logf(sg);
    }
    #pragma unroll
    for (int off = 16; off; off >>= 1)
        logsum += __shfl_xor_sync(0xffffffffu, logsum, off);
    if ((t & 31) == 0)
        atomicAdd(out + HOUT_ELEMS + s, logsum);

    // h1 passthrough
    for (int idx = t; idx < NSQC*256; idx += 256) {
        int ch = idx >> 8;
        int l  = l0 + (idx & 255);
        size_t off = ((size_t)s*NSQ + ch) * LL + l;
        out[off] = h[off];
    }
}

// ============================================================================
extern "C" void kernel_launch(void* const* d_in, const int* in_sizes, int n_in,
                              void* d_out, int out_size)
{
    const float* h   = (const float*)d_in[0];
    const float* emb = (const float*)d_in[1];
    const float* Wa  = (const float*)d_in[2];
    const float* ba  = (const float*)d_in[3];
    const float* Wb  = (const float*)d_in[4];
    const float* bb  = (const float*)d_in[5];
    const float* W1  = (const float*)d_in[6];
    const float* b1  = (const float*)d_in[7];
    const float* W2  = (const float*)d_in[8];
    const float* b2  = (const float*)d_in[9];
    float* out = (float*)d_out;

    static bool attr_set = false;
    if (!attr_set) {
        cudaFuncSetAttribute(gemm_mma_kernel,
                             cudaFuncAttributeMaxDynamicSharedMemorySize, GSMEM_TOTAL);
        cudaFuncSetAttribute(conv2_kernel,
                             cudaFuncAttributeMaxDynamicSharedMemorySize, CONV2_SMEM);
        attr_set = true;
    }

    dynw_kernel<<<S, 256>>>(emb, Wa, ba, Wb, bb, out + HOUT_ELEMS);
    w1cvt_kernel<<<CC, 256>>>(W1);
    dwconv_kernel<<<dim3(8, 8, S), 256>>>(h);
    gemm_mma_kernel<<<dim3(16, 4, S), 256, GSMEM_TOTAL>>>(b1);
    conv2_kernel<<<dim3(8, S), 256, CONV2_SMEM>>>(h, W2, b2, out);
}

// round 8
// speedup vs baseline: 4.9235x; 1.1794x over previous
#include <cuda_runtime.h>
#include <cuda_bf16.h>
#include <math.h>
#include <stdint.h>

// Problem constants
#define S    64
#define NSQ  32
#define NSQC 16
#define LL   2048
#define CC   512
#define EE   128
#define HOUT_ELEMS (S*NSQ*LL)      // 4194304

typedef unsigned long long u64;
typedef unsigned int u32;

// ---------------- scratch (device globals; no allocations allowed) ----------
__device__ float         g_w[S*CC*3];                 // dyn conv weights [s][c][k]
__device__ float         g_b[S*CC];                   // dyn conv bias    [s][c]
__device__ __nv_bfloat16 g_xh[(size_t)S*LL*CC];       // 128 MB  xT hi  [s][l][c]
__device__ __nv_bfloat16 g_xl[(size_t)S*LL*CC];       // 128 MB  xT lo
__device__ __nv_bfloat16 g_w1h[CC*CC];                // W1 hi bf16 [o][c]
__device__ __nv_bfloat16 g_w1l[CC*CC];                // W1 lo bf16
__device__ __nv_bfloat16 g_yh[(size_t)S*LL*CC];       // 128 MB  yT hi  [s][l][c]
__device__ __nv_bfloat16 g_yl[(size_t)S*LL*CC];       // 128 MB  yT lo
__device__ __nv_bfloat16 g_w2h[3*32*CC];              // W2 hi [tap][o][c]
__device__ __nv_bfloat16 g_w2l[3*32*CC];              // W2 lo

// ---------------- mma / ldmatrix / cp.async helpers (sm_80-baseline ISA) ----
__device__ __forceinline__ u32 smem_u32(const void* p) {
    u32 a; asm("{ .reg .u64 t; cvta.to.shared.u64 t, %1; cvt.u32.u64 %0, t; }"
               : "=r"(a) : "l"(p));
    return a;
}
__device__ __forceinline__ void ldm4(u32* r, u32 addr) {
    asm volatile("ldmatrix.sync.aligned.m8n8.x4.shared.b16 {%0,%1,%2,%3}, [%4];"
                 : "=r"(r[0]), "=r"(r[1]), "=r"(r[2]), "=r"(r[3]) : "r"(addr));
}
__device__ __forceinline__ void mma16816(float* d, const u32* a, const u32* b) {
    asm volatile("mma.sync.aligned.m16n8k16.row.col.f32.bf16.bf16.f32 "
                 "{%0,%1,%2,%3}, {%4,%5,%6,%7}, {%8,%9}, {%0,%1,%2,%3};"
                 : "+f"(d[0]), "+f"(d[1]), "+f"(d[2]), "+f"(d[3])
                 : "r"(a[0]), "r"(a[1]), "r"(a[2]), "r"(a[3]), "r"(b[0]), "r"(b[1]));
}
#define CP16(sm, gp)      asm volatile("cp.async.cg.shared.global [%0], [%1], 16;" :: "r"(sm), "l"(gp))
#define CP16Z(sm, gp, sz) asm volatile("cp.async.cg.shared.global [%0], [%1], 16, %2;" :: "r"(sm), "l"(gp), "r"(sz))
#define CP_COMMIT()   asm volatile("cp.async.commit_group;" ::: "memory")
#define CP_WAIT0()    asm volatile("cp.async.wait_group 0;" ::: "memory")

// main-gemm smem tile: 128 rows x 64 bytes, 16B chunks XOR-swizzled
__device__ __forceinline__ u32 soff(int r, int c) {
    return (u32)(r*64 + ((c ^ ((r >> 1) & 3)) * 16));
}

// ============================================================================
// Kernel A: dynamic weights (emb GEMV) + zero logdet
// ============================================================================
__global__ void dynw_kernel(const float* __restrict__ emb,
                            const float* __restrict__ Wa,
                            const float* __restrict__ ba,
                            const float* __restrict__ Wb,
                            const float* __restrict__ bb,
                            float* __restrict__ logdet)
{
    int s = blockIdx.x;
    __shared__ float e[EE];
    int t = threadIdx.x;
    if (t < EE) e[t] = emb[s*EE + t];
    __syncthreads();

    for (int r = t; r < CC*3 + CC; r += blockDim.x) {
        const float* row; float bias; float* outp;
        if (r < CC*3) { row = Wa + (size_t)r*EE; bias = ba[r]; outp = &g_w[s*CC*3 + r]; }
        else { int r2 = r - CC*3; row = Wb + (size_t)r2*EE; bias = bb[r2]; outp = &g_b[s*CC + r2]; }
        float acc = bias;
        #pragma unroll 8
        for (int k = 0; k < EE; ++k) acc = fmaf(e[k], row[k], acc);
        *outp = acc;
    }
    if (t == 0) logdet[s] = 0.f;
}

// ============================================================================
// Kernel A2: W1 -> bf16 hi/lo split.  grid=512 (o), block=256
// ============================================================================
__global__ void w1cvt_kernel(const float* __restrict__ W1)
{
    int o = blockIdx.x, t = threadIdx.x;
    float2 v = *(const float2*)(W1 + (size_t)o*CC + t*2);
    unsigned short h0 = __bfloat16_as_ushort(__float2bfloat16_rn(v.x));
    unsigned short h1 = __bfloat16_as_ushort(__float2bfloat16_rn(v.y));
    float l0 = v.x - __bfloat162float(__float2bfloat16_rn(v.x));
    float l1 = v.y - __bfloat162float(__float2bfloat16_rn(v.y));
    unsigned short g0 = __bfloat16_as_ushort(__float2bfloat16_rn(l0));
    unsigned short g1 = __bfloat16_as_ushort(__float2bfloat16_rn(l1));
    ((u32*)g_w1h)[o*256 + t] = (u32)h0 | ((u32)h1 << 16);
    ((u32*)g_w1l)[o*256 + t] = (u32)g0 | ((u32)g1 << 16);
}

// ============================================================================
// Kernel A3: W2[o][c][k] -> hi/lo bf16 packed [tap][o][c].  grid=192, 256 thr
// ============================================================================
__global__ void w2cvt_kernel(const float* __restrict__ W2)
{
    int idx = blockIdx.x*256 + threadIdx.x;     // < 3*32*512 = 49152
    int c   = idx & 511;
    int o   = (idx >> 9) & 31;
    int tap = idx >> 14;
    float v = W2[(size_t)o*1536 + c*3 + tap];
    __nv_bfloat16 vh = __float2bfloat16_rn(v);
    float rem = v - __bfloat162float(vh);
    g_w2h[idx] = vh;
    g_w2l[idx] = __float2bfloat16_rn(rem);
}

// ============================================================================
// Kernel B: depthwise conv -> relu -> bf16 hi/lo, TRANSPOSED layout xT[s][l][c]
// grid=(8 ltile, 8 ctile, 64 s), block=256 (one l per thread, 64 c's)
// ============================================================================
__global__ __launch_bounds__(256)
void dwconv_kernel(const float* __restrict__ h)
{
    int lt = blockIdx.x, ct = blockIdx.y, s = blockIdx.z;
    int t = threadIdx.x;
    int l = lt*256 + t;

    __shared__ float wsm[64][4];
    {
        int c = t >> 2, j = t & 3;
        int cg = ct*64 + c;
        wsm[c][j] = (j < 3) ? g_w[s*CC*3 + cg*3 + j] : g_b[s*CC + cg];
    }

    int r0 = ct * 2;
    const float* hp0 = h + ((size_t)s*NSQ + r0) * LL;
    const float* hp1 = h + ((size_t)s*NSQ + r0 + 1) * LL;
    float a0 = (l > 0)      ? hp0[l-1] : 0.f;
    float a1 = hp0[l];
    float a2 = (l < LL-1)   ? hp0[l+1] : 0.f;
    float b0 = (l > 0)      ? hp1[l-1] : 0.f;
    float b1v = hp1[l];
    float b2 = (l < LL-1)   ? hp1[l+1] : 0.f;
    __syncthreads();

    u32 hi[32], lo[32];
    #pragma unroll
    for (int p = 0; p < 32; ++p) {
        u32 hh = 0, ll2 = 0;
        #pragma unroll
        for (int q = 0; q < 2; ++q) {
            int i = p*2 + q;
            float w0 = wsm[i][0], w1 = wsm[i][1], w2 = wsm[i][2], bi = wsm[i][3];
            float v;
            if (i < 32) v = fmaf(w0, a0, fmaf(w1, a1, fmaf(w2, a2, bi)));
            else        v = fmaf(w0, b0, fmaf(w1, b1v, fmaf(w2, b2, bi)));
            v = fmaxf(v, 0.f);
            __nv_bfloat16 vh = __float2bfloat16_rn(v);
            float rem = v - __bfloat162float(vh);
            __nv_bfloat16 vl = __float2bfloat16_rn(rem);
            hh  |= ((u32)__bfloat16_as_ushort(vh)) << (q*16);
            ll2 |= ((u32)__bfloat16_as_ushort(vl)) << (q*16);
        }
        hi[p] = hh; lo[p] = ll2;
    }

    size_t base = ((size_t)s*LL + l) * CC + ct*64;
    uint4* dh = (uint4*)(g_xh + base);
    uint4* dl = (uint4*)(g_xl + base);
    #pragma unroll
    for (int j = 0; j < 8; ++j) {
        dh[j] = make_uint4(hi[4*j], hi[4*j+1], hi[4*j+2], hi[4*j+3]);
        dl[j] = make_uint4(lo[4*j], lo[4*j+1], lo[4*j+2], lo[4*j+3]);
    }
}

// ============================================================================
// Kernel C: HMMA GEMM  y = relu(W1 x + b1), bf16 3-term split, fp32 accum.
//   Output written as bf16 hi/lo TRANSPOSED yT[s][l][c] (smem-staged).
//   CTA tile 128x128, K-chunk 32, double-buffered cp.async
//   grid=(16 bn, 4 bm, 64 s), 256 threads
// ============================================================================
#define GT_BYTES 8192
#define GSMEM_TOTAL 65536

__global__ __launch_bounds__(256)
void gemm_mma_kernel(const float* __restrict__ b1)
{
    extern __shared__ __align__(128) char smem[];
    u32 sb = smem_u32(smem);
    int t = threadIdx.x, lane = t & 31, wid = t >> 5;
    int bn = blockIdx.x, bm = blockIdx.y, s = blockIdx.z;
    int wm = wid & 3;
    int wn = wid >> 2;

    int r_ld[2], c_ld[2];
    #pragma unroll
    for (int i = 0; i < 2; ++i) { int idx = t + i*256; r_ld[i] = idx >> 2; c_ld[i] = idx & 3; }

    const __nv_bfloat16* Ah = g_w1h;
    const __nv_bfloat16* Al = g_w1l;
    const __nv_bfloat16* Bh = g_xh + (size_t)s*LL*CC;
    const __nv_bfloat16* Bl = g_xl + (size_t)s*LL*CC;

    auto load_buf = [&](int buf, int kt) {
        u32 base = sb + buf*32768;
        int k0 = kt*32;
        #pragma unroll
        for (int i = 0; i < 2; ++i) {
            int r = r_ld[i], c = c_ld[i];
            u32 so = soff(r, c);
            size_t ka = (size_t)(bm*128 + r)*CC + k0 + c*8;
            size_t kb = (size_t)(bn*128 + r)*CC + k0 + c*8;
            CP16(base + 0*GT_BYTES + so, Ah + ka);
            CP16(base + 1*GT_BYTES + so, Al + ka);
            CP16(base + 2*GT_BYTES + so, Bh + kb);
            CP16(base + 3*GT_BYTES + so, Bl + kb);
        }
    };

    float acc[2][8][4];
    #pragma unroll
    for (int i = 0; i < 2; ++i)
        #pragma unroll
        for (int j = 0; j < 8; ++j)
            #pragma unroll
            for (int q = 0; q < 4; ++q) acc[i][j][q] = 0.f;

    load_buf(0, 0); CP_COMMIT();

    int buf = 0;
    for (int kt = 0; kt < 16; ++kt) {
        CP_WAIT0();
        __syncthreads();
        if (kt < 15) { load_buf(buf ^ 1, kt + 1); CP_COMMIT(); }

        u32 base = sb + buf*32768;
        #pragma unroll
        for (int ks = 0; ks < 2; ++ks) {
            u32 a_h[2][4], a_l[2][4];
            #pragma unroll
            for (int ti = 0; ti < 2; ++ti) {
                int row = wm*32 + ti*16 + (lane & 15);
                int ch  = ks*2 + (lane >> 4);
                u32 so = soff(row, ch);
                ldm4(a_h[ti], base + 0*GT_BYTES + so);
                ldm4(a_l[ti], base + 1*GT_BYTES + so);
            }
            u32 b_h[8][2], b_l[8][2];
            #pragma unroll
            for (int g = 0; g < 4; ++g) {
                int row = wn*64 + g*16 + (lane & 7) + 8*(lane >> 4);
                int ch  = ks*2 + ((lane >> 3) & 1);
                u32 so = soff(row, ch);
                u32 rh[4], rl[4];
                ldm4(rh, base + 2*GT_BYTES + so);
                ldm4(rl, base + 3*GT_BYTES + so);
                b_h[2*g][0] = rh[0]; b_h[2*g][1] = rh[1];
                b_h[2*g+1][0] = rh[2]; b_h[2*g+1][1] = rh[3];
                b_l[2*g][0] = rl[0]; b_l[2*g][1] = rl[1];
                b_l[2*g+1][0] = rl[2]; b_l[2*g+1][1] = rl[3];
            }
            #pragma unroll
            for (int i = 0; i < 2; ++i)
                #pragma unroll
                for (int j = 0; j < 8; ++j) {
                    mma16816(acc[i][j], a_h[i], b_h[j]);
                    mma16816(acc[i][j], a_h[i], b_l[j]);
                    mma16816(acc[i][j], a_l[i], b_h[j]);
                }
        }
        buf ^= 1;
    }

    // ---- epilogue: relu(+bias) -> bf16 hi/lo, transpose via smem ----
    __syncthreads();                       // smem buffers no longer needed
    {
        auto stb = [&](int lc, int rc, float v) {
            __nv_bfloat16 vh = __float2bfloat16_rn(v);
            float rem = v - __bfloat162float(vh);
            __nv_bfloat16 vl = __float2bfloat16_rn(rem);
            *(__nv_bfloat16*)(smem + lc*256 + rc*2)         = vh;   // hi tile [l][o]
            *(__nv_bfloat16*)(smem + 32768 + lc*256 + rc*2) = vl;   // lo tile
        };
        #pragma unroll
        for (int i = 0; i < 2; ++i) {
            int rA = wm*32 + i*16 + (lane >> 2);
            int rB = rA + 8;
            float bA = b1[bm*128 + rA], bB = b1[bm*128 + rB];
            #pragma unroll
            for (int j = 0; j < 8; ++j) {
                int lc = wn*64 + j*8 + 2*(lane & 3);
                float* d = acc[i][j];
                stb(lc,   rA, fmaxf(d[0] + bA, 0.f));
                stb(lc+1, rA, fmaxf(d[1] + bA, 0.f));
                stb(lc,   rB, fmaxf(d[2] + bB, 0.f));
                stb(lc+1, rB, fmaxf(d[3] + bB, 0.f));
            }
        }
    }
    __syncthreads();
    {
        int lr = t >> 1, half = t & 1;
        size_t gbase = ((size_t)s*LL + bn*128 + lr)*CC + bm*128 + half*64;
        #pragma unroll
        for (int q = 0; q < 8; ++q) {
            uint4 vh = *(uint4*)(smem + lr*256 + half*128 + q*16);
            uint4 vl = *(uint4*)(smem + 32768 + lr*256 + half*128 + q*16);
            *(uint4*)(g_yh + gbase + q*8) = vh;
            *(uint4*)(g_yl + gbase + q*8) = vl;
        }
    }
}

// ============================================================================
// Kernel D: conv2 via HMMA.  out[o][l] = sum_{c,k} W2[o][c][k] y[c][l+k-1]
//   A = W2 packed [tap][o(32)][c], B = yT[l][c] rows (tap shift = row offset).
//   M=32, N=256 per CTA, K = 512 c x 3 taps, c-chunks of 32 double-buffered.
//   8 warps: warp tile 32m x 32n. Fused sigmoid/coupling/logdet/h1-copy.
//   grid=(8 ltile, 64 s), 256 threads
// ============================================================================
#define C2_BT   20640          // B tile: 258 rows x 80B
#define C2_AT   7680           // A tile: 96 rows x 80B
#define C2_BB(b) ((b)*2*C2_BT)             // Bh; Bl = +C2_BT
#define C2_AB(b) (82560 + (b)*2*C2_AT)     // Ah; Al = +C2_AT
#define C2_SMEM  113280

__global__ __launch_bounds__(256)
void conv2_mma_kernel(const float* __restrict__ h,
                      const float* __restrict__ b2,
                      float* __restrict__ out)
{
    extern __shared__ __align__(128) char smem[];
    u32 sb = smem_u32(smem);
    int t = threadIdx.x, lane = t & 31, wid = t >> 5;
    int lt = blockIdx.x, s = blockIdx.y;
    int l0 = lt * 256;

    const __nv_bfloat16* Yh = g_yh + (size_t)s*LL*CC;
    const __nv_bfloat16* Yl = g_yl + (size_t)s*LL*CC;

    auto load_cc = [&](int buf, int cc) {
        u32 bB = sb + C2_BB(buf);
        for (int idx = t; idx < 1032; idx += 256) {       // 258 rows x 4 chunks
            int r = idx >> 2, ch = idx & 3;
            int l = l0 - 1 + r;
            bool ok = ((unsigned)l < (unsigned)LL);
            u32 sz = ok ? 16u : 0u;
            size_t goff = (size_t)(ok ? l : 0)*CC + cc*32 + ch*8;
            u32 dst = bB + r*80 + ch*16;
            CP16Z(dst,         Yh + goff, sz);
            CP16Z(dst + C2_BT, Yl + goff, sz);
        }
        u32 bA = sb + C2_AB(buf);
        for (int idx = t; idx < 384; idx += 256) {        // 96 rows x 4 chunks
            int r = idx >> 2, ch = idx & 3;
            size_t goff = (size_t)r*CC + cc*32 + ch*8;
            u32 dst = bA + r*80 + ch*16;
            CP16(dst,         g_w2h + goff);
            CP16(dst + C2_AT, g_w2l + goff);
        }
    };

    float acc[2][4][4];
    #pragma unroll
    for (int i = 0; i < 2; ++i)
        #pragma unroll
        for (int j = 0; j < 4; ++j)
            #pragma unroll
            for (int q = 0; q < 4; ++q) acc[i][j][q] = 0.f;

    load_cc(0, 0); CP_COMMIT();

    int buf = 0;
    for (int cc = 0; cc < 16; ++cc) {
        CP_WAIT0();
        __syncthreads();
        if (cc < 15) { load_cc(buf ^ 1, cc + 1); CP_COMMIT(); }

        u32 bB = sb + C2_BB(buf);
        u32 bA = sb + C2_AB(buf);
        #pragma unroll
        for (int tap = 0; tap < 3; ++tap) {
            #pragma unroll
            for (int ks = 0; ks < 2; ++ks) {
                u32 a_h[2][4], a_l[2][4];
                #pragma unroll
                for (int ti = 0; ti < 2; ++ti) {
                    int row = tap*32 + ti*16 + (lane & 15);
                    int ch  = ks*2 + (lane >> 4);
                    u32 ad = bA + row*80 + ch*16;
                    ldm4(a_h[ti], ad);
                    ldm4(a_l[ti], ad + C2_AT);
                }
                u32 b_h[4][2], b_l[4][2];
                #pragma unroll
                for (int g = 0; g < 2; ++g) {
                    int row = wid*32 + g*16 + (lane & 7) + 8*(lane >> 4) + tap;
                    int ch  = ks*2 + ((lane >> 3) & 1);
                    u32 ad = bB + row*80 + ch*16;
                    u32 rh[4], rl[4];
                    ldm4(rh, ad);
                    ldm4(rl, ad + C2_BT);
                    b_h[2*g][0] = rh[0]; b_h[2*g][1] = rh[1];
                    b_h[2*g+1][0] = rh[2]; b_h[2*g+1][1] = rh[3];
                    b_l[2*g][0] = rl[0]; b_l[2*g][1] = rl[1];
                    b_l[2*g+1][0] = rl[2]; b_l[2*g+1][1] = rl[3];
                }
                #pragma unroll
                for (int i = 0; i < 2; ++i)
                    #pragma unroll
                    for (int j = 0; j < 4; ++j) {
                        mma16816(acc[i][j], a_h[i], b_h[j]);
                        mma16816(acc[i][j], a_h[i], b_l[j]);
                        mma16816(acc[i][j], a_l[i], b_h[j]);
                    }
            }
        }
        buf ^= 1;
    }

    // ---- fused epilogue: i=0 frags are s-channels (o 0..15), i=1 are m ----
    int o2a = lane >> 2, o2b = o2a + 8;
    float bsA = b2[o2a],      bsB = b2[o2b];
    float bmA = b2[16 + o2a], bmB = b2[16 + o2b];
    const float* h2A = h + ((size_t)s*NSQ + 16 + o2a)*LL;
    const float* h2B = h + ((size_t)s*NSQ + 16 + o2b)*LL;
    float* oA = out + ((size_t)s*NSQ + 16 + o2a)*LL;
    float* oB = out + ((size_t)s*NSQ + 16 + o2b)*LL;

    float logsum = 0.f;
    #pragma unroll
    for (int j = 0; j < 4; ++j) {
        int l = l0 + wid*32 + j*8 + 2*(lane & 3);
        float2 hA = *(const float2*)(h2A + l);
        float2 hB = *(const float2*)(h2B + l);
        float sg0 = 1.f/(1.f + expf(-(acc[0][j][0] + bsA + 2.f))) + 1e-7f;
        float sg1 = 1.f/(1.f + expf(-(acc[0][j][1] + bsA + 2.f))) + 1e-7f;
        float sg2 = 1.f/(1.f + expf(-(acc[0][j][2] + bsB + 2.f))) + 1e-7f;
        float sg3 = 1.f/(1.f + expf(-(acc[0][j][3] + bsB + 2.f))) + 1e-7f;
        float2 rA = make_float2(sg0*(hA.x + acc[1][j][0] + bmA),
                                sg1*(hA.y + acc[1][j][1] + bmA));
        float2 rB = make_float2(sg2*(hB.x + acc[1][j][2] + bmB),
                                sg3*(hB.y + acc[1][j][3] + bmB));
        *(float2*)(oA + l) = rA;
        *(float2*)(oB + l) = rB;
        logsum += logf(sg0) + logf(sg1) + logf(sg2) + logf(sg3);
    }
    #pragma unroll
    for (int off = 16; off; off >>= 1)
        logsum += __shfl_xor_sync(0xffffffffu, logsum, off);
    if (lane == 0)
        atomicAdd(out + HOUT_ELEMS + s, logsum);

    // h1 passthrough for this l-tile
    for (int idx = t; idx < NSQC*256; idx += 256) {
        int ch = idx >> 8;
        int l  = l0 + (idx & 255);
        size_t off = ((size_t)s*NSQ + ch)*LL + l;
        out[off] = h[off];
    }
}

// ============================================================================
extern "C" void kernel_launch(void* const* d_in, const int* in_sizes, int n_in,
                              void* d_out, int out_size)
{
    const float* h   = (const float*)d_in[0];
    const float* emb = (const float*)d_in[1];
    const float* Wa  = (const float*)d_in[2];
    const float* ba  = (const float*)d_in[3];
    const float* Wb  = (const float*)d_in[4];
    const float* bb  = (const float*)d_in[5];
    const float* W1  = (const float*)d_in[6];
    const float* b1  = (const float*)d_in[7];
    const float* W2  = (const float*)d_in[8];
    const float* b2  = (const float*)d_in[9];
    float* out = (float*)d_out;

    static bool attr_set = false;
    if (!attr_set) {
        cudaFuncSetAttribute(gemm_mma_kernel,
                             cudaFuncAttributeMaxDynamicSharedMemorySize, GSMEM_TOTAL);
        cudaFuncSetAttribute(conv2_mma_kernel,
                             cudaFuncAttributeMaxDynamicSharedMemorySize, C2_SMEM);
        attr_set = true;
    }

    dynw_kernel<<<S, 256>>>(emb, Wa, ba, Wb, bb, out + HOUT_ELEMS);
    w1cvt_kernel<<<CC, 256>>>(W1);
    w2cvt_kernel<<<192, 256>>>(W2);
    dwconv_kernel<<<dim3(8, 8, S), 256>>>(h);
    gemm_mma_kernel<<<dim3(16, 4, S), 256, GSMEM_TOTAL>>>(b1);
    conv2_mma_kernel<<<dim3(8, S), 256, C2_SMEM>>>(h, b2, out);
}